// round 3
// baseline (speedup 1.0000x reference)
#include <cuda_runtime.h>
#include <cuda_bf16.h>

// Composite coefficients:
// per head h (4 heads), base = h*25:
//   [0..8]   P[i][j]  : u_i = sum_j P[i][j]*z_last[j] + p[i]    (scaled by 1/sqrt(dk))
//   [9..11]  p[i]
//   [12..14] r[i]     : d = sum_i r[i]*z_last[i] + s
//   [15]     s
//   [16..24] G[c][i]  : out[c] += sum_i G[c][i]*zbar[i]
// [100..102] g0[c]    : constant term of output
__device__ float g_comp[104];

__global__ void precompute_kernel(const float* __restrict__ W_in, const float* __restrict__ b_in,
                                  const float* __restrict__ W_q,  const float* __restrict__ b_q,
                                  const float* __restrict__ W_k,  const float* __restrict__ b_k,
                                  const float* __restrict__ W_v,  const float* __restrict__ b_v,
                                  const float* __restrict__ W_o,  const float* __restrict__ b_o)
{
    __shared__ float Aq[32][3], Ak[32][3], Av[32][3];
    __shared__ float cq[32], ck[32], cv[32];
    const int t = threadIdx.x;   // 128 threads

    // Phase 1: compose q/k/v projections with the input projection.
    // x_j = sum_i W_in[j,i] z_i + b_in[j];  q_o = sum_j W_q[o,j] x_j + b_q[o]
    for (int idx = t; idx < 96; idx += blockDim.x) {
        const int o = idx / 3, i = idx % 3;
        float aq = 0.f, ak = 0.f, av = 0.f;
        for (int j = 0; j < 32; j++) {
            const float win = W_in[j * 3 + i];
            aq += W_q[o * 32 + j] * win;
            ak += W_k[o * 32 + j] * win;
            av += W_v[o * 32 + j] * win;
        }
        Aq[o][i] = aq; Ak[o][i] = ak; Av[o][i] = av;
    }
    for (int o = t; o < 32; o += blockDim.x) {
        float q = b_q[o], k = b_k[o], v = b_v[o];
        for (int j = 0; j < 32; j++) {
            const float bi = b_in[j];
            q += W_q[o * 32 + j] * bi;
            k += W_k[o * 32 + j] * bi;
            v += W_v[o * 32 + j] * bi;
        }
        cq[o] = q; ck[o] = k; cv[o] = v;
    }
    __syncthreads();

    const float scale = 0.35355339059327373f;  // 1/sqrt(8)

    // Phase 2: per-head bilinear composites.
    for (int idx = t; idx < 103; idx += blockDim.x) {
        if (idx < 100) {
            const int h = idx / 25, e = idx % 25;
            const int base = h * 8;
            float val = 0.f;
            if (e < 9) {                        // P[i][j] = scale * sum_d Ak[d][i]*Aq[d][j]
                const int i = e / 3, j = e % 3;
                for (int d = 0; d < 8; d++) val += Ak[base + d][i] * Aq[base + d][j];
                val *= scale;
            } else if (e < 12) {                // p[i] = scale * sum_d Ak[d][i]*cq[d]
                const int i = e - 9;
                for (int d = 0; d < 8; d++) val += Ak[base + d][i] * cq[base + d];
                val *= scale;
            } else if (e < 15) {                // r[i] = scale * sum_d Aq[d][i]*ck[d]
                const int i = e - 12;
                for (int d = 0; d < 8; d++) val += Aq[base + d][i] * ck[base + d];
                val *= scale;
            } else if (e == 15) {               // s = scale * cq . ck
                for (int d = 0; d < 8; d++) val += cq[base + d] * ck[base + d];
                val *= scale;
            } else {                            // G[c][i] = sum_d W_o[c][base+d]*Av[d][i]
                const int e2 = e - 16;
                const int c = e2 / 3, i = e2 % 3;
                for (int d = 0; d < 8; d++) val += W_o[c * 32 + base + d] * Av[base + d][i];
            }
            g_comp[h * 25 + e] = val;
        } else {                                // g0[c] = b_o[c] + W_o[c] . cv
            const int c = idx - 100;
            float val = b_o[c];
            for (int d = 0; d < 32; d++) val += W_o[c * 32 + d] * cv[d];
            g_comp[100 + c] = val;
        }
    }
}

// One thread per (b, h, w) position. HW = 256*256 = 65536, T = 8, C = 3.
__global__ void __launch_bounds__(256) attn_main_kernel(const float* __restrict__ z,
                                                        float* __restrict__ out,
                                                        int n_pos)
{
    __shared__ float C[104];
    if (threadIdx.x < 104) C[threadIdx.x] = g_comp[threadIdx.x];
    __syncthreads();

    const int p = blockIdx.x * blockDim.x + threadIdx.x;
    if (p >= n_pos) return;

    const int b  = p >> 16;          // p / 65536
    const int hw = p & 65535;        // p % 65536

    // z layout (B, T=8, C=3, H, W): element (b,t,c,hw) at ((b*8+t)*3+c)*65536 + hw
    float zz[8][3];
    const float* zp = z + (size_t)b * 8 * 3 * 65536 + hw;
#pragma unroll
    for (int t = 0; t < 8; t++)
#pragma unroll
        for (int c = 0; c < 3; c++)
            zz[t][c] = zp[(size_t)(t * 3 + c) * 65536];

    const float zl0 = zz[7][0], zl1 = zz[7][1], zl2 = zz[7][2];
    float o0 = C[100], o1 = C[101], o2 = C[102];

#pragma unroll
    for (int h = 0; h < 4; h++) {
        const float* Ph = &C[h * 25];
        const float u0 = Ph[0] * zl0 + Ph[1] * zl1 + Ph[2] * zl2 + Ph[9];
        const float u1 = Ph[3] * zl0 + Ph[4] * zl1 + Ph[5] * zl2 + Ph[10];
        const float u2 = Ph[6] * zl0 + Ph[7] * zl1 + Ph[8] * zl2 + Ph[11];
        const float d  = Ph[12] * zl0 + Ph[13] * zl1 + Ph[14] * zl2 + Ph[15];

        float sc[8];
        float m = -1e30f;
#pragma unroll
        for (int s = 0; s < 8; s++) {
            sc[s] = u0 * zz[s][0] + u1 * zz[s][1] + u2 * zz[s][2] + d;
            m = fmaxf(m, sc[s]);
        }
        float sum = 0.f, zb0 = 0.f, zb1 = 0.f, zb2 = 0.f;
#pragma unroll
        for (int s = 0; s < 8; s++) {
            const float e = __expf(sc[s] - m);
            sum += e;
            zb0 += e * zz[s][0];
            zb1 += e * zz[s][1];
            zb2 += e * zz[s][2];
        }
        const float inv = __fdividef(1.f, sum);
        zb0 *= inv; zb1 *= inv; zb2 *= inv;
        o0 += Ph[16] * zb0 + Ph[17] * zb1 + Ph[18] * zb2;
        o1 += Ph[19] * zb0 + Ph[20] * zb1 + Ph[21] * zb2;
        o2 += Ph[22] * zb0 + Ph[23] * zb1 + Ph[24] * zb2;
    }

    // out layout (B, 3, H, W): element (b,c,hw) at (b*3+c)*65536 + hw
    float* op = out + (size_t)b * 3 * 65536 + hw;
    op[0]             = o0;
    op[1 * 65536]     = o1;
    op[2 * 65536]     = o2;
}

extern "C" void kernel_launch(void* const* d_in, const int* in_sizes, int n_in,
                              void* d_out, int out_size)
{
    const float* z    = (const float*)d_in[0];
    const float* W_in = (const float*)d_in[1];
    const float* b_in = (const float*)d_in[2];
    const float* W_q  = (const float*)d_in[3];
    const float* b_q  = (const float*)d_in[4];
    const float* W_k  = (const float*)d_in[5];
    const float* b_k  = (const float*)d_in[6];
    const float* W_v  = (const float*)d_in[7];
    const float* b_v  = (const float*)d_in[8];
    const float* W_o  = (const float*)d_in[9];
    const float* b_o  = (const float*)d_in[10];
    float* out = (float*)d_out;

    precompute_kernel<<<1, 128>>>(W_in, b_in, W_q, b_q, W_k, b_k, W_v, b_v, W_o, b_o);

    const int n_pos = out_size / 3;          // B * H * W = 262144
    const int threads = 256;
    const int blocks = (n_pos + threads - 1) / threads;
    attn_main_kernel<<<blocks, threads>>>(z, out, n_pos);
}